// round 13
// baseline (speedup 1.0000x reference)
#include <cuda_runtime.h>
#include <cuda_bf16.h>
#include <math.h>
#include <float.h>
#include <stdint.h>

// ---------------------------------------------------------------- constants
#define D        256
#define NC       1024
#define NF       8192
#define NTOT     9216
#define TM       128          // rows per CTA
#define TN       128          // embeddings per tile
#define KSTEPS   17           // 272 aug cols / 16
#define SXB      560          // row stride bytes: 280 bf16 (272 aug + 8 pad)
#define TILE_B   (TM * SXB)   // 71680 bytes per tile
#define NTHR     512
#define NWARP    16

#define QOFF      1
#define FPERP_OFF 12632065
#define CPERP_OFF 12632066
#define ENC_OFF   12632067

// dynamic smem layout (bytes)
#define SM_X      0
#define SM_E0     TILE_B              // 71680
#define SM_E1     (2 * TILE_B)        // 143360
#define SM_MBAR   (3 * TILE_B)        // 215040: full0,full1,empty0,empty1
#define SM_TOTAL  (3 * TILE_B + 64)   // 215104

__device__ int    g_counts[NTOT];
__device__ double g_loss[2];
__device__ __align__(16) float g_e2[NTOT];
// pre-padded, K-augmented bf16 embeddings: row stride 560B, cols 0..255 data,
// col 256 = h, col 257 = r with h + r ~= -e2/2 (two-term bf16 split)
__device__ __align__(128) unsigned char g_ebf[(size_t)NTOT * SXB];

// ---------------------------------------------------------------- helpers
static __device__ __forceinline__ uint32_t smem_u32(const void* p) {
    uint32_t a;
    asm("{ .reg .u64 t; cvta.to.shared.u64 t, %1; cvt.u32.u64 %0, t; }"
        : "=r"(a) : "l"(p));
    return a;
}
static __device__ __forceinline__ uint32_t pk(float lo, float hi) {
    uint32_t r;
    asm("cvt.rn.bf16x2.f32 %0, %1, %2;" : "=r"(r) : "f"(hi), "f"(lo));
    return r;
}
static __device__ __forceinline__ bool dlt(float da, int ia, float db, int ib) {
    return (da < db) || (da == db && ia < ib);
}
static __device__ __forceinline__ void ins3(float d, int i,
        float& d0, int& i0, float& d1, int& i1, float& d2, int& i2) {
    if (dlt(d, i, d2, i2)) {
        if (dlt(d, i, d1, i1)) {
            d2 = d1; i2 = i1;
            if (dlt(d, i, d0, i0)) { d1 = d0; i1 = i0; d0 = d; i0 = i; }
            else                    { d1 = d;  i1 = i; }
        } else { d2 = d; i2 = i; }
    }
}
// insert-largest (approx scores tracked as raw acc = dot - e2/2; larger = closer)
static __device__ __forceinline__ void insL(float s, int i,
        float& t0, int& i0, float& t1, int& i1, float& t2, int& i2) {
    if (s > t2) {
        if (s > t1) {
            t2 = t1; i2 = i1;
            if (s > t0) { t1 = t0; i1 = i0; t0 = s; i0 = i; }
            else         { t1 = s;  i1 = i; }
        } else { t2 = s; i2 = i; }
    }
}

#define LDSM4(r, addr) \
    asm volatile("ldmatrix.sync.aligned.m8n8.x4.shared.b16 {%0,%1,%2,%3}, [%4];" \
        : "=r"((r)[0]), "=r"((r)[1]), "=r"((r)[2]), "=r"((r)[3]) : "r"(addr))

// NOTE: non-volatile — register-only effects; lets ptxas interleave with LDSM
#define MMA16816(c, a, b0_, b1_) \
    asm("mma.sync.aligned.m16n8k16.row.col.f32.bf16.bf16.f32 " \
        "{%0,%1,%2,%3}, {%4,%5,%6,%7}, {%8,%9}, {%0,%1,%2,%3};" \
        : "+f"((c)[0]), "+f"((c)[1]), "+f"((c)[2]), "+f"((c)[3]) \
        : "r"((a)[0]), "r"((a)[1]), "r"((a)[2]), "r"((a)[3]), \
          "r"(b0_), "r"(b1_))

#define MBAR_INIT(a, n) \
    asm volatile("mbarrier.init.shared.b64 [%0], %1;" :: "r"(a), "r"(n) : "memory")
#define MBAR_ARRIVE(a) \
    asm volatile("mbarrier.arrive.shared.b64 _, [%0];" :: "r"(a) : "memory")
#define MBAR_EXPECT_TX(a, bytes) \
    asm volatile("mbarrier.arrive.expect_tx.shared.b64 _, [%0], %1;" \
                 :: "r"(a), "r"(bytes) : "memory")
#define BULK_CP(dst, src, bytes, mbar) \
    asm volatile("cp.async.bulk.shared::cluster.global.mbarrier::complete_tx::bytes " \
                 "[%0], [%1], %2, [%3];" \
                 :: "r"(dst), "l"(src), "r"(bytes), "r"(mbar) : "memory")
#define MBAR_WAIT(a, par) do {                                               \
    uint32_t _m = (a), _p = (par), _d;                                       \
    asm volatile("{\n\t.reg .pred p;\n\t"                                    \
        "mbarrier.try_wait.parity.acquire.cta.shared::cta.b64 p, [%1], %2;\n\t" \
        "selp.b32 %0, 1, 0, p;\n\t}" : "=r"(_d) : "r"(_m), "r"(_p) : "memory"); \
    if (!_d) {                                                               \
        asm volatile("{\n\t.reg .pred P1;\n\tWL%=: \n\t"                     \
            "mbarrier.try_wait.parity.acquire.cta.shared::cta.b64 P1, [%0], %1, 0x989680;\n\t" \
            "@P1 bra.uni WD%=;\n\tbra.uni WL%=;\n\tWD%=: \n\t}"              \
            :: "r"(_m), "r"(_p) : "memory");                                 \
    }                                                                        \
} while (0)

// ---------------------------------------------------------------- small kernels
__global__ void vq_zero() {
    int i = blockIdx.x * 256 + threadIdx.x;   // 36*256 = 9216
    g_counts[i] = 0;
    if (i < 2) g_loss[i] = 0.0;
}

__global__ void vq_e2(const float* __restrict__ Ec, const float* __restrict__ Ef) {
    int gw   = (blockIdx.x * blockDim.x + threadIdx.x) >> 5;
    int lane = threadIdx.x & 31;
    if (gw >= NTOT) return;
    const float* row = (gw < NC) ? (Ec + (size_t)gw * D)
                                 : (Ef + (size_t)(gw - NC) * D);
    const float4* r4 = (const float4*)row;
    float4 a = r4[lane];
    float4 b = r4[lane + 32];
    float s = a.x*a.x + a.y*a.y + a.z*a.z + a.w*a.w
            + b.x*b.x + b.y*b.y + b.z*b.z + b.w*b.w;
    #pragma unroll
    for (int o = 16; o > 0; o >>= 1) s += __shfl_xor_sync(0xffffffffu, s, o);
    if (lane == 0) g_e2[gw] = s;
}

// build padded + K-augmented bf16 embedding matrix (row stride 560B)
__global__ void vq_cvt(const float* __restrict__ Ec, const float* __restrict__ Ef) {
    int idx = blockIdx.x * 256 + threadIdx.x;   // 1260*256 = 322560 = 9216*35
    int row = idx / 35;
    int ch  = idx - row * 35;                   // 16B chunk within 560B row
    uint4 pv = make_uint4(0u, 0u, 0u, 0u);
    if (ch < 32) {
        const float* src = (row < NC) ? (Ec + (size_t)row * D + ch * 8)
                                      : (Ef + (size_t)(row - NC) * D + ch * 8);
        float4 a = ((const float4*)src)[0];
        float4 b = ((const float4*)src)[1];
        pv.x = pk(a.x, a.y); pv.y = pk(a.z, a.w);
        pv.z = pk(b.x, b.y); pv.w = pk(b.z, b.w);
    } else if (ch == 32) {
        // two-term bf16 split of -e2/2: col256 = h, col257 = r
        float v = -0.5f * g_e2[row];
        __nv_bfloat16 hb = __float2bfloat16(v);
        float res = v - __bfloat162float(hb);
        __nv_bfloat16 rb = __float2bfloat16(res);
        pv.x = (uint32_t)__bfloat16_as_ushort(hb)
             | ((uint32_t)__bfloat16_as_ushort(rb) << 16);
    }
    *(uint4*)(g_ebf + (size_t)row * SXB + ch * 16) = pv;
}

// ---------------------------------------------------------------- main kernel
__global__ void __launch_bounds__(NTHR, 1) vq_main(
        const float* __restrict__ feats,
        const float* __restrict__ Ec,
        const float* __restrict__ Ef,
        float* __restrict__ out)
{
    extern __shared__ char smc[];
    const uint32_t sbase = smem_u32(smc);
    const int tid  = threadIdx.x;
    const int wid  = tid >> 5;
    const int lane = tid & 31;
    const int wm   = wid & 3;       // warp row group (4 x 32 rows)
    const int wn   = wid >> 2;      // warp col group (4 x 32 embs)
    const int g8   = lane >> 2;     // 0..7
    const int tid4 = lane & 3;

    // role of this CTA
    const float* Xf; int ntiles, gbase_e, valid, gbase, lslot;
    if (blockIdx.x == 0) {
        Xf = feats;                 ntiles = NC / TN;  gbase_e = 0;
        valid = 64;  gbase = 0;     lslot = 0;
    } else {
        int b = blockIdx.x - 1;
        Xf = feats + (size_t)(64 + b * TM) * D;
        ntiles = NF / TN;  gbase_e = NC;
        valid = TM;  gbase = 64 + b * TM;  lslot = 1;
    }

    const uint32_t full0  = sbase + SM_MBAR;
    const uint32_t full1  = sbase + SM_MBAR + 8;
    const uint32_t empty0 = sbase + SM_MBAR + 16;
    const uint32_t empty1 = sbase + SM_MBAR + 24;

    if (tid == 0) {
        MBAR_INIT(full0, 1);  MBAR_INIT(full1, 1);
        MBAR_INIT(empty0, NWARP); MBAR_INIT(empty1, NWARP);
    }

    // convert X block to augmented bf16 smem (pad rows -> 0; aug cols = 1,1)
    for (int q = tid; q < TM * 35; q += NTHR) {
        int row = q / 35, ch = q - row * 35;
        uint4 pv = make_uint4(0u, 0u, 0u, 0u);
        if (ch < 32) {
            if (row < valid) {
                const float4* xs = (const float4*)(Xf + (size_t)row * D + ch * 8);
                float4 a = xs[0], b = xs[1];
                pv.x = pk(a.x, a.y); pv.y = pk(a.z, a.w);
                pv.z = pk(b.x, b.y); pv.w = pk(b.z, b.w);
            }
        } else if (ch == 32) {
            pv.x = 0x3F803F80u;                  // cols 256,257 = 1.0, 1.0 (bf16)
        }
        *(uint4*)(smc + SM_X + (size_t)row * SXB + ch * 16) = pv;
    }
    __syncthreads();   // X ready + mbarriers initialized

    // prologue: bulk-load tiles 0 and 1
    if (tid == 0) {
        MBAR_EXPECT_TX(full0, TILE_B);
        BULK_CP(sbase + SM_E0, g_ebf + (size_t)gbase_e * SXB, TILE_B, full0);
        MBAR_EXPECT_TX(full1, TILE_B);
        BULK_CP(sbase + SM_E1, g_ebf + (size_t)(gbase_e + TN) * SXB, TILE_B, full1);
    }

    // ldmatrix per-thread offsets
    const int arow  = wm * 32 + (lane & 7) + ((lane >> 3) & 1) * 8;
    const int akoff = (lane >> 4) * 8;
    const uint32_t aoff0 = (uint32_t)(arow * SXB + akoff * 2);
    const uint32_t aoff1 = aoff0 + 16 * SXB;
    const int brow  = (lane & 7) + ((lane >> 4) & 1) * 8;
    const int bkoff = ((lane >> 3) & 1) * 8;
    const uint32_t boff0 = (uint32_t)((wn * 32 + brow) * SXB + bkoff * 2);
    const uint32_t boff1 = boff0 + 16 * SXB;

    // per-thread approx top-3 per owned row, tracked as LARGEST acc
    float td[4][3]; int ti[4][3];
    #pragma unroll
    for (int li = 0; li < 4; li++)
        #pragma unroll
        for (int q = 0; q < 3; q++) { td[li][q] = -FLT_MAX; ti[li][q] = 0x7fffffff; }

    const uint32_t xb = sbase + SM_X;

    // ---------------- main tile loop (no block-wide syncs) -------------------
    for (int t = 0; t < ntiles; t++) {
        const int bsel = t & 1;
        const uint32_t fullb  = bsel ? full1 : full0;
        const uint32_t emptyb = bsel ? empty1 : empty0;
        MBAR_WAIT(fullb, (uint32_t)((t >> 1) & 1));

        const uint32_t eb = sbase + (bsel ? SM_E1 : SM_E0);

        float acc[2][4][4];
        #pragma unroll
        for (int mt = 0; mt < 2; mt++)
            #pragma unroll
            for (int nt = 0; nt < 4; nt++)
                #pragma unroll
                for (int q = 0; q < 4; q++) acc[mt][nt][q] = 0.f;

        // software-pipelined fragment loop, LDSM/MMA interleaved so one MIO
        // stall never blocks a burst of ready tensor work
        uint32_t af[2][2][4], bf[2][2][4];
        LDSM4(af[0][0], xb + aoff0);
        LDSM4(af[0][1], xb + aoff1);
        LDSM4(bf[0][0], eb + boff0);
        LDSM4(bf[0][1], eb + boff1);
        #pragma unroll
        for (int ks = 0; ks < KSTEPS; ks++) {
            const int cur = ks & 1, nxt = cur ^ 1;
            const uint32_t kb = (ks + 1) * 32;
            const bool more = (ks < KSTEPS - 1);
            if (more) LDSM4(af[nxt][0], xb + aoff0 + kb);
            MMA16816(acc[0][0], af[cur][0], bf[cur][0][0], bf[cur][0][1]);
            MMA16816(acc[0][1], af[cur][0], bf[cur][0][2], bf[cur][0][3]);
            if (more) LDSM4(af[nxt][1], xb + aoff1 + kb);
            MMA16816(acc[1][0], af[cur][1], bf[cur][0][0], bf[cur][0][1]);
            MMA16816(acc[1][1], af[cur][1], bf[cur][0][2], bf[cur][0][3]);
            if (more) LDSM4(bf[nxt][0], eb + boff0 + kb);
            MMA16816(acc[0][2], af[cur][0], bf[cur][1][0], bf[cur][1][1]);
            MMA16816(acc[0][3], af[cur][0], bf[cur][1][2], bf[cur][1][3]);
            if (more) LDSM4(bf[nxt][1], eb + boff1 + kb);
            MMA16816(acc[1][2], af[cur][1], bf[cur][1][0], bf[cur][1][1]);
            MMA16816(acc[1][3], af[cur][1], bf[cur][1][2], bf[cur][1][3]);
        }

        // this warp is done reading buffer bsel
        if (lane == 0) MBAR_ARRIVE(emptyb);

        // refill buffer bsel with tile t+2 once all 16 warps released it
        if (t + 2 < ntiles && tid == 0) {
            MBAR_WAIT(emptyb, (uint32_t)((t >> 1) & 1));
            MBAR_EXPECT_TX(fullb, TILE_B);
            BULK_CP(eb, g_ebf + (size_t)(gbase_e + (t + 2) * TN) * SXB,
                    TILE_B, fullb);
        }

        // ---- batched epilogue: one fmaxf tree + ONE predicate per list ------
        const int ebase = gbase_e + t * TN;
        #pragma unroll
        for (int mt = 0; mt < 2; mt++) {
            #pragma unroll
            for (int half = 0; half < 2; half++) {     // c{0,1} vs c{2,3}
                const int li = mt * 2 + half;
                float m = fmaxf(
                    fmaxf(fmaxf(acc[mt][0][2*half], acc[mt][0][2*half+1]),
                          fmaxf(acc[mt][1][2*half], acc[mt][1][2*half+1])),
                    fmaxf(fmaxf(acc[mt][2][2*half], acc[mt][2][2*half+1]),
                          fmaxf(acc[mt][3][2*half], acc[mt][3][2*half+1])));
                if (m > td[li][2]) {                    // rare path
                    #pragma unroll
                    for (int nt = 0; nt < 4; nt++) {
                        #pragma unroll
                        for (int c = 0; c < 2; c++) {
                            float s = acc[mt][nt][2*half + c];
                            int ge = ebase + wn * 32 + nt * 8 + tid4 * 2 + c;
                            insL(s, ge, td[li][0], ti[li][0],
                                       td[li][1], ti[li][1],
                                       td[li][2], ti[li][2]);
                        }
                    }
                }
            }
        }
    }
    __syncthreads();   // all tiles done; smem free for reuse

    // ---------------- merge: 16 threads x top3 -> 48 cands per row -----------
    float* cd  = (float*)smc;                    // [128][48] floats
    int*   ci  = (int*)(smc + 24576);            // [128][48] ints
    float* cd8 = (float*)(smc + 49152);          // [128][8]
    int*   ci8 = (int*)(smc + 53248);            // [128][8]
    int*   sel = (int*)(smc + 57344);            // [128][3]

    const int slot = wn * 4 + tid4;              // 0..15 per row
    // list li = mt*2 + half -> row = wm*32 + g8 + half*8 + mt*16
    #pragma unroll
    for (int mt = 0; mt < 2; mt++) {
        #pragma unroll
        for (int half = 0; half < 2; half++) {
            int li = mt * 2 + half;
            int row = wm * 32 + g8 + half * 8 + mt * 16;
            #pragma unroll
            for (int q = 0; q < 3; q++) {
                cd[row * 48 + slot * 3 + q] = -td[li][q];   // back to distance
                ci[row * 48 + slot * 3 + q] = ti[li][q];
            }
        }
    }
    __syncthreads();

    // approx top-8 of 48 (selection with tie-break; destructive)
    if (tid < valid) {
        for (int s = 0; s < 8; s++) {
            float bd = FLT_MAX; int bi = 0x7fffffff; int bj = -1;
            for (int j = 0; j < 48; j++) {
                float dv = cd[tid * 48 + j]; int iv = ci[tid * 48 + j];
                if (dlt(dv, iv, bd, bi)) { bd = dv; bi = iv; bj = j; }
            }
            cd[tid * 48 + bj] = FLT_MAX; ci[tid * 48 + bj] = 0x7fffffff;
            cd8[tid * 8 + s] = bd;  ci8[tid * 8 + s] = bi;
        }
    }
    __syncthreads();

    // ---------------- exact fp32 rescore of 8 candidates per row ------------
    for (int it = wid; it < valid * 8; it += NWARP) {
        int row = it >> 3, c = it & 7;
        int idx = ci8[row * 8 + c];
        const float* erow = (idx < NC) ? (Ec + (size_t)idx * D)
                                       : (Ef + (size_t)(idx - NC) * D);
        const float4* e4 = (const float4*)erow;
        const float4* x4 = (const float4*)(Xf + (size_t)row * D);
        float4 ea = e4[lane * 2], ebv = e4[lane * 2 + 1];
        float4 xa = x4[lane * 2], xbv = x4[lane * 2 + 1];
        float dot = ea.x*xa.x + ea.y*xa.y + ea.z*xa.z + ea.w*xa.w
                  + ebv.x*xbv.x + ebv.y*xbv.y + ebv.z*xbv.z + ebv.w*xbv.w;
        #pragma unroll
        for (int o = 16; o > 0; o >>= 1) dot += __shfl_xor_sync(0xffffffffu, dot, o);
        if (lane == 0) cd8[row * 8 + c] = g_e2[idx] - 2.f * dot;
    }
    __syncthreads();

    // exact top-3 with index tie-break (matches lax.top_k stability)
    if (tid < valid) {
        float d0 = FLT_MAX, d1 = FLT_MAX, d2 = FLT_MAX;
        int   i0 = 0x7fffffff, i1 = 0x7fffffff, i2 = 0x7fffffff;
        #pragma unroll
        for (int s = 0; s < 8; s++)
            ins3(cd8[tid * 8 + s], ci8[tid * 8 + s], d0, i0, d1, i1, d2, i2);
        sel[tid * 3 + 0] = i0;
        sel[tid * 3 + 1] = i1;
        sel[tid * 3 + 2] = i2;
    }
    __syncthreads();

    // ---------------- gather + write quantized/indices + loss + counts ------
    float lsum = 0.f;
    for (int j = wid; j < valid * 3; j += NWARP) {
        int r  = j / 3;
        int kk = j - r * 3;
        int idx = sel[j];
        int g  = gbase + r;
        const float* erow = (idx < NC) ? (Ec + (size_t)idx * D)
                                       : (Ef + (size_t)(idx - NC) * D);
        const float4* e4 = (const float4*)erow;
        const float4* x4 = (const float4*)(Xf + (size_t)r * D);
        float4 v0 = e4[lane * 2], v1 = e4[lane * 2 + 1];
        float4 x0 = x4[lane * 2], x1 = x4[lane * 2 + 1];
        size_t qb = QOFF + ((size_t)g * 3 + kk) * D + lane * 8;
        out[qb + 0] = v0.x; out[qb + 1] = v0.y; out[qb + 2] = v0.z; out[qb + 3] = v0.w;
        out[qb + 4] = v1.x; out[qb + 5] = v1.y; out[qb + 6] = v1.z; out[qb + 7] = v1.w;
        float dx;
        dx = v0.x - x0.x; lsum += dx * dx;
        dx = v0.y - x0.y; lsum += dx * dx;
        dx = v0.z - x0.z; lsum += dx * dx;
        dx = v0.w - x0.w; lsum += dx * dx;
        dx = v1.x - x1.x; lsum += dx * dx;
        dx = v1.y - x1.y; lsum += dx * dx;
        dx = v1.z - x1.z; lsum += dx * dx;
        dx = v1.w - x1.w; lsum += dx * dx;
        if (lane == 0) {
            out[ENC_OFF + (size_t)g * 3 + kk] = (float)idx;
            atomicAdd(&g_counts[idx], 1);
        }
    }
    #pragma unroll
    for (int o = 16; o > 0; o >>= 1) lsum += __shfl_xor_sync(0xffffffffu, lsum, o);
    if (lane == 0) atomicAdd(&g_loss[lslot], (double)lsum);
}

// ---------------------------------------------------------------- finalize
__global__ void vq_finalize(float* __restrict__ out) {
    int tid = threadIdx.x;                    // 1024 threads
    float hf = 0.f;
    for (int i = tid; i < NF; i += 1024) {
        float avg = (float)g_counts[NC + i] * (1.0f / 16384.0f);
        hf += avg * logf(avg + 1e-10f);
    }
    float avgc = (float)g_counts[tid] * (1.0f / 64.0f);
    float hc = avgc * logf(avgc + 1e-10f);

    __shared__ float redf[32], redc[32];
    int lane = tid & 31, w = tid >> 5;
    #pragma unroll
    for (int o = 16; o > 0; o >>= 1) {
        hf += __shfl_xor_sync(0xffffffffu, hf, o);
        hc += __shfl_xor_sync(0xffffffffu, hc, o);
    }
    if (lane == 0) { redf[w] = hf; redc[w] = hc; }
    __syncthreads();
    if (tid < 32) {
        float f = redf[tid], c = redc[tid];
        #pragma unroll
        for (int o = 16; o > 0; o >>= 1) {
            f += __shfl_xor_sync(0xffffffffu, f, o);
            c += __shfl_xor_sync(0xffffffffu, c, o);
        }
        if (tid == 0) {
            out[FPERP_OFF] = expf(-f);
            out[CPERP_OFF] = expf(-c);
            out[0] = (float)(1.25 * (g_loss[0] / (64.0 * 3.0 * 256.0)
                                   + g_loss[1] / (16384.0 * 3.0 * 256.0)));
        }
    }
}

// ---------------------------------------------------------------- launcher
extern "C" void kernel_launch(void* const* d_in, const int* in_sizes, int n_in,
                              void* d_out, int out_size) {
    (void)in_sizes; (void)n_in; (void)out_size;
    const float* feats = (const float*)d_in[0];
    const float* Ec    = (const float*)d_in[1];
    const float* Ef    = (const float*)d_in[2];
    float* out = (float*)d_out;

    cudaFuncSetAttribute(vq_main, cudaFuncAttributeMaxDynamicSharedMemorySize, SM_TOTAL);

    vq_zero<<<36, 256>>>();
    vq_e2<<<NTOT / 8, 256>>>(Ec, Ef);
    vq_cvt<<<1260, 256>>>(Ec, Ef);
    vq_main<<<129, NTHR, SM_TOTAL>>>(feats, Ec, Ef, out);
    vq_finalize<<<1, 1024>>>(out);
}

// round 15
// speedup vs baseline: 1.0145x; 1.0145x over previous
#include <cuda_runtime.h>
#include <cuda_bf16.h>
#include <math.h>
#include <float.h>
#include <stdint.h>

// ---------------------------------------------------------------- constants
#define D        256
#define NC       1024
#define NF       8192
#define NTOT     9216
#define TM       128          // rows per CTA
#define TN       128          // embeddings per tile
#define KSTEPS   17           // 272 aug cols / 16
#define SXB      560          // row stride bytes: 280 bf16 (272 aug + 8 pad)
#define TILE_B   (TM * SXB)   // 71680 bytes per tile
#define NTHR     512
#define NWARP    16
#define NCTA     129

#define QOFF      1
#define FPERP_OFF 12632065
#define CPERP_OFF 12632066
#define ENC_OFF   12632067

// dynamic smem layout (bytes)
#define SM_X      0
#define SM_E0     TILE_B              // 71680
#define SM_E1     (2 * TILE_B)        // 143360
#define SM_MBAR   (3 * TILE_B)        // 215040: full0,full1,empty0,empty1
#define SM_TOTAL  (3 * TILE_B + 64)   // 215104

__device__ int    g_counts[NTOT];
__device__ double g_loss[2];
__device__ int    g_done;
__device__ __align__(16) float g_e2[NTOT];
// pre-padded, K-augmented bf16 embeddings: row stride 560B, cols 0..255 data,
// col 256 = h, col 257 = r with h + r ~= -e2/2 (two-term bf16 split)
__device__ __align__(128) unsigned char g_ebf[(size_t)NTOT * SXB];

// ---------------------------------------------------------------- helpers
static __device__ __forceinline__ uint32_t smem_u32(const void* p) {
    uint32_t a;
    asm("{ .reg .u64 t; cvta.to.shared.u64 t, %1; cvt.u32.u64 %0, t; }"
        : "=r"(a) : "l"(p));
    return a;
}
static __device__ __forceinline__ uint32_t pk(float lo, float hi) {
    uint32_t r;
    asm("cvt.rn.bf16x2.f32 %0, %1, %2;" : "=r"(r) : "f"(hi), "f"(lo));
    return r;
}
static __device__ __forceinline__ bool dlt(float da, int ia, float db, int ib) {
    return (da < db) || (da == db && ia < ib);
}
static __device__ __forceinline__ void ins3(float d, int i,
        float& d0, int& i0, float& d1, int& i1, float& d2, int& i2) {
    if (dlt(d, i, d2, i2)) {
        if (dlt(d, i, d1, i1)) {
            d2 = d1; i2 = i1;
            if (dlt(d, i, d0, i0)) { d1 = d0; i1 = i0; d0 = d; i0 = i; }
            else                    { d1 = d;  i1 = i; }
        } else { d2 = d; i2 = i; }
    }
}
// insert-largest (approx scores tracked as raw acc = dot - e2/2; larger = closer)
static __device__ __forceinline__ void insL(float s, int i,
        float& t0, int& i0, float& t1, int& i1, float& t2, int& i2) {
    if (s > t2) {
        if (s > t1) {
            t2 = t1; i2 = i1;
            if (s > t0) { t1 = t0; i1 = i0; t0 = s; i0 = i; }
            else         { t1 = s;  i1 = i; }
        } else { t2 = s; i2 = i; }
    }
}

#define LDSM4(r, addr) \
    asm volatile("ldmatrix.sync.aligned.m8n8.x4.shared.b16 {%0,%1,%2,%3}, [%4];" \
        : "=r"((r)[0]), "=r"((r)[1]), "=r"((r)[2]), "=r"((r)[3]) : "r"(addr))

#define MMA16816(c, a, b0_, b1_) \
    asm("mma.sync.aligned.m16n8k16.row.col.f32.bf16.bf16.f32 " \
        "{%0,%1,%2,%3}, {%4,%5,%6,%7}, {%8,%9}, {%0,%1,%2,%3};" \
        : "+f"((c)[0]), "+f"((c)[1]), "+f"((c)[2]), "+f"((c)[3]) \
        : "r"((a)[0]), "r"((a)[1]), "r"((a)[2]), "r"((a)[3]), \
          "r"(b0_), "r"(b1_))

#define MBAR_INIT(a, n) \
    asm volatile("mbarrier.init.shared.b64 [%0], %1;" :: "r"(a), "r"(n) : "memory")
#define MBAR_ARRIVE(a) \
    asm volatile("mbarrier.arrive.shared.b64 _, [%0];" :: "r"(a) : "memory")
#define MBAR_EXPECT_TX(a, bytes) \
    asm volatile("mbarrier.arrive.expect_tx.shared.b64 _, [%0], %1;" \
                 :: "r"(a), "r"(bytes) : "memory")
#define BULK_CP(dst, src, bytes, mbar) \
    asm volatile("cp.async.bulk.shared::cluster.global.mbarrier::complete_tx::bytes " \
                 "[%0], [%1], %2, [%3];" \
                 :: "r"(dst), "l"(src), "r"(bytes), "r"(mbar) : "memory")
#define MBAR_WAIT(a, par) do {                                               \
    uint32_t _m = (a), _p = (par), _d;                                       \
    asm volatile("{\n\t.reg .pred p;\n\t"                                    \
        "mbarrier.try_wait.parity.acquire.cta.shared::cta.b64 p, [%1], %2;\n\t" \
        "selp.b32 %0, 1, 0, p;\n\t}" : "=r"(_d) : "r"(_m), "r"(_p) : "memory"); \
    if (!_d) {                                                               \
        asm volatile("{\n\t.reg .pred P1;\n\tWL%=: \n\t"                     \
            "mbarrier.try_wait.parity.acquire.cta.shared::cta.b64 P1, [%0], %1, 0x989680;\n\t" \
            "@P1 bra.uni WD%=;\n\tbra.uni WL%=;\n\tWD%=: \n\t}"              \
            :: "r"(_m), "r"(_p) : "memory");                                 \
    }                                                                        \
} while (0)

// ---------------------------------------------------------------- prep kernel
// One warp per embedding row: compute e2, write g_e2 + padded/augmented bf16
// row. Blocks 0..35 also zero g_counts; block 0 zeros g_loss and g_done.
__global__ void vq_prep(const float* __restrict__ Ec, const float* __restrict__ Ef) {
    const int tid  = threadIdx.x;          // 256 threads = 8 warps
    const int lane = tid & 31;
    const int row  = blockIdx.x * 8 + (tid >> 5);   // 1152 blocks -> 9216 rows

    if (blockIdx.x < 36) {
        g_counts[blockIdx.x * 256 + tid] = 0;
        if (blockIdx.x == 0 && tid < 3) {
            if (tid < 2) g_loss[tid] = 0.0;
            else         g_done = 0;
        }
    }

    const float* src = (row < NC) ? (Ec + (size_t)row * D)
                                  : (Ef + (size_t)(row - NC) * D);
    const float4* r4 = (const float4*)src;
    float4 a = r4[lane * 2];
    float4 b = r4[lane * 2 + 1];
    float s = a.x*a.x + a.y*a.y + a.z*a.z + a.w*a.w
            + b.x*b.x + b.y*b.y + b.z*b.z + b.w*b.w;
    #pragma unroll
    for (int o = 16; o > 0; o >>= 1) s += __shfl_xor_sync(0xffffffffu, s, o);
    // all lanes now hold e2
    if (lane == 0) g_e2[row] = s;

    unsigned char* dst = g_ebf + (size_t)row * SXB;
    // data chunk: cols lane*8 .. lane*8+7
    uint4 pv;
    pv.x = pk(a.x, a.y); pv.y = pk(a.z, a.w);
    pv.z = pk(b.x, b.y); pv.w = pk(b.z, b.w);
    *(uint4*)(dst + lane * 16) = pv;
    // aug + pad chunks 32..34
    if (lane < 3) {
        uint4 zv = make_uint4(0u, 0u, 0u, 0u);
        if (lane == 0) {
            float v = -0.5f * s;
            __nv_bfloat16 hb = __float2bfloat16(v);
            float res = v - __bfloat162float(hb);
            __nv_bfloat16 rb = __float2bfloat16(res);
            zv.x = (uint32_t)__bfloat16_as_ushort(hb)
                 | ((uint32_t)__bfloat16_as_ushort(rb) << 16);
        }
        *(uint4*)(dst + (32 + lane) * 16) = zv;
    }
}

// ---------------------------------------------------------------- main kernel
__global__ void __launch_bounds__(NTHR, 1) vq_main(
        const float* __restrict__ feats,
        const float* __restrict__ Ec,
        const float* __restrict__ Ef,
        float* __restrict__ out)
{
    extern __shared__ char smc[];
    const uint32_t sbase = smem_u32(smc);
    const int tid  = threadIdx.x;
    const int wid  = tid >> 5;
    const int lane = tid & 31;
    const int wm   = wid & 3;       // warp row group (4 x 32 rows)
    const int wn   = wid >> 2;      // warp col group (4 x 32 embs)
    const int g8   = lane >> 2;     // 0..7
    const int tid4 = lane & 3;

    // role of this CTA
    const float* Xf; int ntiles, gbase_e, valid, gbase, lslot;
    if (blockIdx.x == 0) {
        Xf = feats;                 ntiles = NC / TN;  gbase_e = 0;
        valid = 64;  gbase = 0;     lslot = 0;
    } else {
        int b = blockIdx.x - 1;
        Xf = feats + (size_t)(64 + b * TM) * D;
        ntiles = NF / TN;  gbase_e = NC;
        valid = TM;  gbase = 64 + b * TM;  lslot = 1;
    }

    const uint32_t full0  = sbase + SM_MBAR;
    const uint32_t full1  = sbase + SM_MBAR + 8;
    const uint32_t empty0 = sbase + SM_MBAR + 16;
    const uint32_t empty1 = sbase + SM_MBAR + 24;

    if (tid == 0) {
        MBAR_INIT(full0, 1);  MBAR_INIT(full1, 1);
        MBAR_INIT(empty0, NWARP); MBAR_INIT(empty1, NWARP);
    }

    // convert X block to augmented bf16 smem (pad rows -> 0; aug cols = 1,1)
    for (int q = tid; q < TM * 35; q += NTHR) {
        int row = q / 35, ch = q - row * 35;
        uint4 pv = make_uint4(0u, 0u, 0u, 0u);
        if (ch < 32) {
            if (row < valid) {
                const float4* xs = (const float4*)(Xf + (size_t)row * D + ch * 8);
                float4 a = xs[0], b = xs[1];
                pv.x = pk(a.x, a.y); pv.y = pk(a.z, a.w);
                pv.z = pk(b.x, b.y); pv.w = pk(b.z, b.w);
            }
        } else if (ch == 32) {
            pv.x = 0x3F803F80u;                  // cols 256,257 = 1.0, 1.0 (bf16)
        }
        *(uint4*)(smc + SM_X + (size_t)row * SXB + ch * 16) = pv;
    }
    __syncthreads();   // X ready + mbarriers initialized

    // prologue: bulk-load tiles 0 and 1
    if (tid == 0) {
        MBAR_EXPECT_TX(full0, TILE_B);
        BULK_CP(sbase + SM_E0, g_ebf + (size_t)gbase_e * SXB, TILE_B, full0);
        MBAR_EXPECT_TX(full1, TILE_B);
        BULK_CP(sbase + SM_E1, g_ebf + (size_t)(gbase_e + TN) * SXB, TILE_B, full1);
    }

    // ldmatrix per-thread offsets
    const int arow  = wm * 32 + (lane & 7) + ((lane >> 3) & 1) * 8;
    const int akoff = (lane >> 4) * 8;
    const uint32_t aoff0 = (uint32_t)(arow * SXB + akoff * 2);
    const uint32_t aoff1 = aoff0 + 16 * SXB;
    const int brow  = (lane & 7) + ((lane >> 4) & 1) * 8;
    const int bkoff = ((lane >> 3) & 1) * 8;
    const uint32_t boff0 = (uint32_t)((wn * 32 + brow) * SXB + bkoff * 2);
    const uint32_t boff1 = boff0 + 16 * SXB;

    // per-thread approx top-3 per owned row, tracked as LARGEST acc
    float td[4][3]; int ti[4][3];
    #pragma unroll
    for (int li = 0; li < 4; li++)
        #pragma unroll
        for (int q = 0; q < 3; q++) { td[li][q] = -FLT_MAX; ti[li][q] = 0x7fffffff; }

    const uint32_t xb = sbase + SM_X;

    // ---------------- main tile loop (no block-wide syncs) -------------------
    for (int t = 0; t < ntiles; t++) {
        const int bsel = t & 1;
        const uint32_t fullb  = bsel ? full1 : full0;
        const uint32_t emptyb = bsel ? empty1 : empty0;
        MBAR_WAIT(fullb, (uint32_t)((t >> 1) & 1));

        const uint32_t eb = sbase + (bsel ? SM_E1 : SM_E0);

        float acc[2][4][4];
        #pragma unroll
        for (int mt = 0; mt < 2; mt++)
            #pragma unroll
            for (int nt = 0; nt < 4; nt++)
                #pragma unroll
                for (int q = 0; q < 4; q++) acc[mt][nt][q] = 0.f;

        // software-pipelined fragment loop
        uint32_t af[2][2][4], bf[2][2][4];
        LDSM4(af[0][0], xb + aoff0);
        LDSM4(af[0][1], xb + aoff1);
        LDSM4(bf[0][0], eb + boff0);
        LDSM4(bf[0][1], eb + boff1);
        #pragma unroll
        for (int ks = 0; ks < KSTEPS; ks++) {
            const int cur = ks & 1, nxt = cur ^ 1;
            const uint32_t kb = (ks + 1) * 32;
            const bool more = (ks < KSTEPS - 1);
            if (more) LDSM4(af[nxt][0], xb + aoff0 + kb);
            MMA16816(acc[0][0], af[cur][0], bf[cur][0][0], bf[cur][0][1]);
            MMA16816(acc[0][1], af[cur][0], bf[cur][0][2], bf[cur][0][3]);
            if (more) LDSM4(af[nxt][1], xb + aoff1 + kb);
            MMA16816(acc[1][0], af[cur][1], bf[cur][0][0], bf[cur][0][1]);
            MMA16816(acc[1][1], af[cur][1], bf[cur][0][2], bf[cur][0][3]);
            if (more) LDSM4(bf[nxt][0], eb + boff0 + kb);
            MMA16816(acc[0][2], af[cur][0], bf[cur][1][0], bf[cur][1][1]);
            MMA16816(acc[0][3], af[cur][0], bf[cur][1][2], bf[cur][1][3]);
            if (more) LDSM4(bf[nxt][1], eb + boff1 + kb);
            MMA16816(acc[1][2], af[cur][1], bf[cur][1][0], bf[cur][1][1]);
            MMA16816(acc[1][3], af[cur][1], bf[cur][1][2], bf[cur][1][3]);
        }

        // this warp is done reading buffer bsel
        if (lane == 0) MBAR_ARRIVE(emptyb);

        // refill buffer bsel with tile t+2 once all 16 warps released it
        if (t + 2 < ntiles && tid == 0) {
            MBAR_WAIT(emptyb, (uint32_t)((t >> 1) & 1));
            MBAR_EXPECT_TX(fullb, TILE_B);
            BULK_CP(eb, g_ebf + (size_t)(gbase_e + (t + 2) * TN) * SXB,
                    TILE_B, fullb);
        }

        // ---- batched epilogue: one fmaxf tree + ONE predicate per list ------
        const int ebase = gbase_e + t * TN;
        #pragma unroll
        for (int mt = 0; mt < 2; mt++) {
            #pragma unroll
            for (int half = 0; half < 2; half++) {     // c{0,1} vs c{2,3}
                const int li = mt * 2 + half;
                float m = fmaxf(
                    fmaxf(fmaxf(acc[mt][0][2*half], acc[mt][0][2*half+1]),
                          fmaxf(acc[mt][1][2*half], acc[mt][1][2*half+1])),
                    fmaxf(fmaxf(acc[mt][2][2*half], acc[mt][2][2*half+1]),
                          fmaxf(acc[mt][3][2*half], acc[mt][3][2*half+1])));
                if (m > td[li][2]) {                    // rare path
                    #pragma unroll
                    for (int nt = 0; nt < 4; nt++) {
                        #pragma unroll
                        for (int c = 0; c < 2; c++) {
                            float s = acc[mt][nt][2*half + c];
                            int ge = ebase + wn * 32 + nt * 8 + tid4 * 2 + c;
                            insL(s, ge, td[li][0], ti[li][0],
                                       td[li][1], ti[li][1],
                                       td[li][2], ti[li][2]);
                        }
                    }
                }
            }
        }
    }
    __syncthreads();   // all tiles done; smem free for reuse

    // ---------------- merge: 16 threads x top3 -> 48 cands per row -----------
    float* cd  = (float*)smc;                    // [128][48] floats
    int*   ci  = (int*)(smc + 24576);            // [128][48] ints
    float* cd8 = (float*)(smc + 49152);          // [128][8]
    int*   ci8 = (int*)(smc + 53248);            // [128][8]
    int*   sel = (int*)(smc + 57344);            // [128][3]

    const int slot = wn * 4 + tid4;              // 0..15 per row
    // list li = mt*2 + half -> row = wm*32 + g8 + half*8 + mt*16
    #pragma unroll
    for (int mt = 0; mt < 2; mt++) {
        #pragma unroll
        for (int half = 0; half < 2; half++) {
            int li = mt * 2 + half;
            int row = wm * 32 + g8 + half * 8 + mt * 16;
            #pragma unroll
            for (int q = 0; q < 3; q++) {
                cd[row * 48 + slot * 3 + q] = -td[li][q];   // back to distance
                ci[row * 48 + slot * 3 + q] = ti[li][q];
            }
        }
    }
    __syncthreads();

    // approx top-8 of 48 (selection with tie-break; destructive)
    if (tid < valid) {
        for (int s = 0; s < 8; s++) {
            float bd = FLT_MAX; int bi = 0x7fffffff; int bj = -1;
            for (int j = 0; j < 48; j++) {
                float dv = cd[tid * 48 + j]; int iv = ci[tid * 48 + j];
                if (dlt(dv, iv, bd, bi)) { bd = dv; bi = iv; bj = j; }
            }
            cd[tid * 48 + bj] = FLT_MAX; ci[tid * 48 + bj] = 0x7fffffff;
            cd8[tid * 8 + s] = bd;  ci8[tid * 8 + s] = bi;
        }
    }
    __syncthreads();

    // ---------------- exact fp32 rescore of 8 candidates per row ------------
    for (int it = wid; it < valid * 8; it += NWARP) {
        int row = it >> 3, c = it & 7;
        int idx = ci8[row * 8 + c];
        const float* erow = (idx < NC) ? (Ec + (size_t)idx * D)
                                       : (Ef + (size_t)(idx - NC) * D);
        const float4* e4 = (const float4*)erow;
        const float4* x4 = (const float4*)(Xf + (size_t)row * D);
        float4 ea = e4[lane * 2], ebv = e4[lane * 2 + 1];
        float4 xa = x4[lane * 2], xbv = x4[lane * 2 + 1];
        float dot = ea.x*xa.x + ea.y*xa.y + ea.z*xa.z + ea.w*xa.w
                  + ebv.x*xbv.x + ebv.y*xbv.y + ebv.z*xbv.z + ebv.w*xbv.w;
        #pragma unroll
        for (int o = 16; o > 0; o >>= 1) dot += __shfl_xor_sync(0xffffffffu, dot, o);
        if (lane == 0) cd8[row * 8 + c] = g_e2[idx] - 2.f * dot;
    }
    __syncthreads();

    // exact top-3 with index tie-break (matches lax.top_k stability)
    if (tid < valid) {
        float d0 = FLT_MAX, d1 = FLT_MAX, d2 = FLT_MAX;
        int   i0 = 0x7fffffff, i1 = 0x7fffffff, i2 = 0x7fffffff;
        #pragma unroll
        for (int s = 0; s < 8; s++)
            ins3(cd8[tid * 8 + s], ci8[tid * 8 + s], d0, i0, d1, i1, d2, i2);
        sel[tid * 3 + 0] = i0;
        sel[tid * 3 + 1] = i1;
        sel[tid * 3 + 2] = i2;
    }
    __syncthreads();

    // ---------------- gather + write quantized/indices + loss + counts ------
    float lsum = 0.f;
    for (int j = wid; j < valid * 3; j += NWARP) {
        int r  = j / 3;
        int kk = j - r * 3;
        int idx = sel[j];
        int g  = gbase + r;
        const float* erow = (idx < NC) ? (Ec + (size_t)idx * D)
                                       : (Ef + (size_t)(idx - NC) * D);
        const float4* e4 = (const float4*)erow;
        const float4* x4 = (const float4*)(Xf + (size_t)r * D);
        float4 v0 = e4[lane * 2], v1 = e4[lane * 2 + 1];
        float4 x0 = x4[lane * 2], x1 = x4[lane * 2 + 1];
        size_t qb = QOFF + ((size_t)g * 3 + kk) * D + lane * 8;
        out[qb + 0] = v0.x; out[qb + 1] = v0.y; out[qb + 2] = v0.z; out[qb + 3] = v0.w;
        out[qb + 4] = v1.x; out[qb + 5] = v1.y; out[qb + 6] = v1.z; out[qb + 7] = v1.w;
        float dx;
        dx = v0.x - x0.x; lsum += dx * dx;
        dx = v0.y - x0.y; lsum += dx * dx;
        dx = v0.z - x0.z; lsum += dx * dx;
        dx = v0.w - x0.w; lsum += dx * dx;
        dx = v1.x - x1.x; lsum += dx * dx;
        dx = v1.y - x1.y; lsum += dx * dx;
        dx = v1.z - x1.z; lsum += dx * dx;
        dx = v1.w - x1.w; lsum += dx * dx;
        if (lane == 0) {
            out[ENC_OFF + (size_t)g * 3 + kk] = (float)idx;
            atomicAdd(&g_counts[idx], 1);
        }
    }
    #pragma unroll
    for (int o = 16; o > 0; o >>= 1) lsum += __shfl_xor_sync(0xffffffffu, lsum, o);
    if (lane == 0) atomicAdd(&g_loss[lslot], (double)lsum);

    // ---------------- last-CTA-done finalize ---------------------------------
    __shared__ int s_last;
    __syncthreads();               // all this CTA's atomics issued
    __threadfence();               // make them globally visible
    if (tid == 0) {
        int old = atomicAdd(&g_done, 1);
        s_last = (old == NCTA - 1) ? 1 : 0;
    }
    __syncthreads();
    if (s_last) {
        __threadfence();           // acquire: see all CTAs' atomics
        float hf = 0.f, hc = 0.f;
        for (int i = tid; i < NF; i += NTHR) {
            float avg = (float)g_counts[NC + i] * (1.0f / 16384.0f);
            hf += avg * logf(avg + 1e-10f);
        }
        for (int i = tid; i < NC; i += NTHR) {
            float avgc = (float)g_counts[i] * (1.0f / 64.0f);
            hc += avgc * logf(avgc + 1e-10f);
        }
        __shared__ float redf[16], redc[16];
        #pragma unroll
        for (int o = 16; o > 0; o >>= 1) {
            hf += __shfl_xor_sync(0xffffffffu, hf, o);
            hc += __shfl_xor_sync(0xffffffffu, hc, o);
        }
        if (lane == 0) { redf[wid] = hf; redc[wid] = hc; }
        __syncthreads();
        if (tid < 32) {
            float f = (tid < 16) ? redf[tid] : 0.f;
            float c = (tid < 16) ? redc[tid] : 0.f;
            #pragma unroll
            for (int o = 8; o > 0; o >>= 1) {
                f += __shfl_xor_sync(0xffffffffu, f, o);
                c += __shfl_xor_sync(0xffffffffu, c, o);
            }
            if (tid == 0) {
                out[FPERP_OFF] = expf(-f);
                out[CPERP_OFF] = expf(-c);
                out[0] = (float)(1.25 * (g_loss[0] / (64.0 * 3.0 * 256.0)
                                       + g_loss[1] / (16384.0 * 3.0 * 256.0)));
            }
        }
    }
}

// ---------------------------------------------------------------- launcher
extern "C" void kernel_launch(void* const* d_in, const int* in_sizes, int n_in,
                              void* d_out, int out_size) {
    (void)in_sizes; (void)n_in; (void)out_size;
    const float* feats = (const float*)d_in[0];
    const float* Ec    = (const float*)d_in[1];
    const float* Ef    = (const float*)d_in[2];
    float* out = (float*)d_out;

    cudaFuncSetAttribute(vq_main, cudaFuncAttributeMaxDynamicSharedMemorySize, SM_TOTAL);

    vq_prep<<<NTOT / 8, 256>>>(Ec, Ef);
    vq_main<<<NCTA, NTHR, SM_TOTAL>>>(feats, Ec, Ef, out);
}

// round 16
// speedup vs baseline: 1.0320x; 1.0173x over previous
#include <cuda_runtime.h>
#include <cuda_bf16.h>
#include <math.h>
#include <float.h>
#include <stdint.h>

// ---------------------------------------------------------------- constants
#define D        256
#define NC       1024
#define NF       8192
#define NTOT     9216
#define TM       128
#define TN       128
#define KSTEPS   17
#define SXB      560
#define TILE_B   (TM * SXB)   // 71680
#define NTHR     512
#define NWARP    16
#define NBLK     128          // feature row blocks
#define NT_P     58           // primary tiles per block
#define NT_H     6            // helper tiles per block
#define NHELP    19
#define NCTA_FIN 129          // primaries + class arrive at g_done

#define QOFF      1
#define FPERP_OFF 12632065
#define CPERP_OFF 12632066
#define ENC_OFF   12632067

#define SM_X      0
#define SM_E0     TILE_B
#define SM_E1     (2 * TILE_B)
#define SM_MBAR   (3 * TILE_B)
#define SM_TOTAL  (3 * TILE_B + 64)

__device__ int    g_counts[NTOT];
__device__ double g_loss[2];
__device__ int    g_done;
__device__ __align__(16) float g_e2[NTOT];
__device__ __align__(128) unsigned char g_ebf[(size_t)NTOT * SXB];
__device__ __align__(128) unsigned char g_xbf[(size_t)NBLK * TILE_B];
__device__ float g_cd[(size_t)NBLK * TM * 48];
__device__ int   g_ci[(size_t)NBLK * TM * 48];
__device__ int   g_xready[NBLK];
__device__ int   g_cflag[NBLK];

// ---------------------------------------------------------------- helpers
static __device__ __forceinline__ uint32_t smem_u32(const void* p) {
    uint32_t a;
    asm("{ .reg .u64 t; cvta.to.shared.u64 t, %1; cvt.u32.u64 %0, t; }"
        : "=r"(a) : "l"(p));
    return a;
}
static __device__ __forceinline__ uint32_t pk(float lo, float hi) {
    uint32_t r;
    asm("cvt.rn.bf16x2.f32 %0, %1, %2;" : "=r"(r) : "f"(hi), "f"(lo));
    return r;
}
static __device__ __forceinline__ bool dlt(float da, int ia, float db, int ib) {
    return (da < db) || (da == db && ia < ib);
}
static __device__ __forceinline__ void ins3(float d, int i,
        float& d0, int& i0, float& d1, int& i1, float& d2, int& i2) {
    if (dlt(d, i, d2, i2)) {
        if (dlt(d, i, d1, i1)) {
            d2 = d1; i2 = i1;
            if (dlt(d, i, d0, i0)) { d1 = d0; i1 = i0; d0 = d; i0 = i; }
            else                    { d1 = d;  i1 = i; }
        } else { d2 = d; i2 = i; }
    }
}
static __device__ __forceinline__ void insL(float s, int i,
        float& t0, int& i0, float& t1, int& i1, float& t2, int& i2) {
    if (s > t2) {
        if (s > t1) {
            t2 = t1; i2 = i1;
            if (s > t0) { t1 = t0; i1 = i0; t0 = s; i0 = i; }
            else         { t1 = s;  i1 = i; }
        } else { t2 = s; i2 = i; }
    }
}

#define LDSM4(r, addr) \
    asm volatile("ldmatrix.sync.aligned.m8n8.x4.shared.b16 {%0,%1,%2,%3}, [%4];" \
        : "=r"((r)[0]), "=r"((r)[1]), "=r"((r)[2]), "=r"((r)[3]) : "r"(addr))

#define MMA16816(c, a, b0_, b1_) \
    asm("mma.sync.aligned.m16n8k16.row.col.f32.bf16.bf16.f32 " \
        "{%0,%1,%2,%3}, {%4,%5,%6,%7}, {%8,%9}, {%0,%1,%2,%3};" \
        : "+f"((c)[0]), "+f"((c)[1]), "+f"((c)[2]), "+f"((c)[3]) \
        : "r"((a)[0]), "r"((a)[1]), "r"((a)[2]), "r"((a)[3]), \
          "r"(b0_), "r"(b1_))

#define MBAR_INIT(a, n) \
    asm volatile("mbarrier.init.shared.b64 [%0], %1;" :: "r"(a), "r"(n) : "memory")
#define MBAR_ARRIVE(a) \
    asm volatile("mbarrier.arrive.shared.b64 _, [%0];" :: "r"(a) : "memory")
#define MBAR_EXPECT_TX(a, bytes) \
    asm volatile("mbarrier.arrive.expect_tx.shared.b64 _, [%0], %1;" \
                 :: "r"(a), "r"(bytes) : "memory")
#define BULK_CP(dst, src, bytes, mbar) \
    asm volatile("cp.async.bulk.shared::cluster.global.mbarrier::complete_tx::bytes " \
                 "[%0], [%1], %2, [%3];" \
                 :: "r"(dst), "l"(src), "r"(bytes), "r"(mbar) : "memory")
#define MBAR_WAIT(a, par) do {                                               \
    uint32_t _m = (a), _p = (par), _d;                                       \
    asm volatile("{\n\t.reg .pred p;\n\t"                                    \
        "mbarrier.try_wait.parity.acquire.cta.shared::cta.b64 p, [%1], %2;\n\t" \
        "selp.b32 %0, 1, 0, p;\n\t}" : "=r"(_d) : "r"(_m), "r"(_p) : "memory"); \
    if (!_d) {                                                               \
        asm volatile("{\n\t.reg .pred P1;\n\tWL%=: \n\t"                     \
            "mbarrier.try_wait.parity.acquire.cta.shared::cta.b64 P1, [%0], %1, 0x989680;\n\t" \
            "@P1 bra.uni WD%=;\n\tbra.uni WL%=;\n\tWD%=: \n\t}"              \
            :: "r"(_m), "r"(_p) : "memory");                                 \
    }                                                                        \
} while (0)

// ---------------------------------------------------------------- prep kernel
__global__ void vq_prep(const float* __restrict__ Ec, const float* __restrict__ Ef) {
    const int tid  = threadIdx.x;          // 256 threads = 8 warps
    const int lane = tid & 31;
    const int row  = blockIdx.x * 8 + (tid >> 5);   // 1152 blocks -> 9216 rows

    if (blockIdx.x < 36) {
        g_counts[blockIdx.x * 256 + tid] = 0;
        if (blockIdx.x == 0 && tid < 3) {
            if (tid < 2) g_loss[tid] = 0.0;
            else         g_done = 0;
        }
        if (blockIdx.x == 1 && tid < NBLK) g_xready[tid] = 0;
        if (blockIdx.x == 2 && tid < NBLK) g_cflag[tid] = 0;
    }

    const float* src = (row < NC) ? (Ec + (size_t)row * D)
                                  : (Ef + (size_t)(row - NC) * D);
    const float4* r4 = (const float4*)src;
    float4 a = r4[lane * 2];
    float4 b = r4[lane * 2 + 1];
    float s = a.x*a.x + a.y*a.y + a.z*a.z + a.w*a.w
            + b.x*b.x + b.y*b.y + b.z*b.z + b.w*b.w;
    #pragma unroll
    for (int o = 16; o > 0; o >>= 1) s += __shfl_xor_sync(0xffffffffu, s, o);
    if (lane == 0) g_e2[row] = s;

    unsigned char* dst = g_ebf + (size_t)row * SXB;
    uint4 pv;
    pv.x = pk(a.x, a.y); pv.y = pk(a.z, a.w);
    pv.z = pk(b.x, b.y); pv.w = pk(b.z, b.w);
    *(uint4*)(dst + lane * 16) = pv;
    if (lane < 3) {
        uint4 zv = make_uint4(0u, 0u, 0u, 0u);
        if (lane == 0) {
            float v = -0.5f * s;
            __nv_bfloat16 hb = __float2bfloat16(v);
            float res = v - __bfloat162float(hb);
            __nv_bfloat16 rb = __float2bfloat16(res);
            zv.x = (uint32_t)__bfloat16_as_ushort(hb)
                 | ((uint32_t)__bfloat16_as_ushort(rb) << 16);
        }
        *(uint4*)(dst + (32 + lane) * 16) = zv;
    }
}

// ---------------------------------------------------------------- main kernel
__global__ void __launch_bounds__(NTHR, 1) vq_main(
        const float* __restrict__ feats,
        const float* __restrict__ Ec,
        const float* __restrict__ Ef,
        float* __restrict__ out)
{
    extern __shared__ char smc[];
    const uint32_t sbase = smem_u32(smc);
    const int tid  = threadIdx.x;
    const int wid  = tid >> 5;
    const int lane = tid & 31;
    const int wm   = wid & 3;
    const int wn   = wid >> 2;
    const int g8   = lane >> 2;
    const int tid4 = lane & 3;

    const uint32_t full0  = sbase + SM_MBAR;
    const uint32_t full1  = sbase + SM_MBAR + 8;
    const uint32_t empty0 = sbase + SM_MBAR + 16;
    const uint32_t empty1 = sbase + SM_MBAR + 24;
    if (tid == 0) {
        MBAR_INIT(full0, 1);  MBAR_INIT(full1, 1);
        MBAR_INIT(empty0, NWARP); MBAR_INIT(empty1, NWARP);
    }

    // ldmatrix per-thread offsets (shared by all roles)
    const int arow  = wm * 32 + (lane & 7) + ((lane >> 3) & 1) * 8;
    const int akoff = (lane >> 4) * 8;
    const uint32_t aoff0 = (uint32_t)(arow * SXB + akoff * 2);
    const uint32_t aoff1 = aoff0 + 16 * SXB;
    const int brow  = (lane & 7) + ((lane >> 4) & 1) * 8;
    const int bkoff = ((lane >> 3) & 1) * 8;
    const uint32_t boff0 = (uint32_t)((wn * 32 + brow) * SXB + bkoff * 2);
    const uint32_t boff1 = boff0 + 16 * SXB;
    const uint32_t xb = sbase + SM_X;

    // =========================== HELPER CTAs ================================
    if (blockIdx.x > NBLK) {
        const int hj  = blockIdx.x - (NBLK + 1);
        const int hb0 = (NBLK * hj) / NHELP;
        const int hb1 = (NBLK * (hj + 1)) / NHELP;
        const int nstream = NT_H * (hb1 - hb0);
        __syncthreads();   // mbarriers visible

        // prologue: E streams 0,1 (tiles 58,59)
        if (tid == 0) {
            MBAR_EXPECT_TX(full0, TILE_B);
            BULK_CP(sbase + SM_E0,
                    g_ebf + (size_t)(NC + 58 * TN) * SXB, TILE_B, full0);
            MBAR_EXPECT_TX(full1, TILE_B);
            BULK_CP(sbase + SM_E1,
                    g_ebf + (size_t)(NC + 59 * TN) * SXB, TILE_B, full1);
        }

        int tglob = 0;
        for (int b = hb0; b < hb1; b++) {
            // wait for primary's converted X block, copy into smem
            if (tid == 0) { while (atomicAdd(&g_xready[b], 0) == 0) {} }
            __syncthreads();
            __threadfence();
            {
                const uint4* src = (const uint4*)(g_xbf + (size_t)b * TILE_B);
                uint4* dst = (uint4*)(smc + SM_X);
                for (int q = tid; q < TILE_B / 16; q += NTHR) dst[q] = src[q];
            }
            __syncthreads();

            float td[4][3]; int ti[4][3];
            #pragma unroll
            for (int li = 0; li < 4; li++)
                #pragma unroll
                for (int q = 0; q < 3; q++) { td[li][q] = -FLT_MAX; ti[li][q] = 0x7fffffff; }

            for (int tp = 0; tp < NT_H; tp++, tglob++) {
                const int slot = tglob & 1;
                const uint32_t fullb  = slot ? full1 : full0;
                const uint32_t emptyb = slot ? empty1 : empty0;
                const uint32_t par = (uint32_t)((tglob >> 1) & 1);
                MBAR_WAIT(fullb, par);
                const uint32_t eb = sbase + (slot ? SM_E1 : SM_E0);

                float acc[2][4][4];
                #pragma unroll
                for (int mt = 0; mt < 2; mt++)
                    #pragma unroll
                    for (int nt = 0; nt < 4; nt++)
                        #pragma unroll
                        for (int q = 0; q < 4; q++) acc[mt][nt][q] = 0.f;

                uint32_t af[2][2][4], bf[2][2][4];
                LDSM4(af[0][0], xb + aoff0);
                LDSM4(af[0][1], xb + aoff1);
                LDSM4(bf[0][0], eb + boff0);
                LDSM4(bf[0][1], eb + boff1);
                #pragma unroll
                for (int ks = 0; ks < KSTEPS; ks++) {
                    const int cur = ks & 1, nxt = cur ^ 1;
                    const uint32_t kb = (ks + 1) * 32;
                    const bool more = (ks < KSTEPS - 1);
                    if (more) LDSM4(af[nxt][0], xb + aoff0 + kb);
                    MMA16816(acc[0][0], af[cur][0], bf[cur][0][0], bf[cur][0][1]);
                    MMA16816(acc[0][1], af[cur][0], bf[cur][0][2], bf[cur][0][3]);
                    if (more) LDSM4(af[nxt][1], xb + aoff1 + kb);
                    MMA16816(acc[1][0], af[cur][1], bf[cur][0][0], bf[cur][0][1]);
                    MMA16816(acc[1][1], af[cur][1], bf[cur][0][2], bf[cur][0][3]);
                    if (more) LDSM4(bf[nxt][0], eb + boff0 + kb);
                    MMA16816(acc[0][2], af[cur][0], bf[cur][1][0], bf[cur][1][1]);
                    MMA16816(acc[0][3], af[cur][0], bf[cur][1][2], bf[cur][1][3]);
                    if (more) LDSM4(bf[nxt][1], eb + boff1 + kb);
                    MMA16816(acc[1][2], af[cur][1], bf[cur][1][0], bf[cur][1][1]);
                    MMA16816(acc[1][3], af[cur][1], bf[cur][1][2], bf[cur][1][3]);
                }
                if (lane == 0) MBAR_ARRIVE(emptyb);
                if (tglob + 2 < nstream && tid == 0) {
                    MBAR_WAIT(emptyb, par);
                    MBAR_EXPECT_TX(fullb, TILE_B);
                    BULK_CP(eb, g_ebf + (size_t)(NC + (58 + ((tglob + 2) % NT_H)) * TN) * SXB,
                            TILE_B, fullb);
                }
                const int ebase = NC + (58 + tp) * TN;
                #pragma unroll
                for (int mt = 0; mt < 2; mt++) {
                    #pragma unroll
                    for (int half = 0; half < 2; half++) {
                        const int li = mt * 2 + half;
                        float m = fmaxf(
                            fmaxf(fmaxf(acc[mt][0][2*half], acc[mt][0][2*half+1]),
                                  fmaxf(acc[mt][1][2*half], acc[mt][1][2*half+1])),
                            fmaxf(fmaxf(acc[mt][2][2*half], acc[mt][2][2*half+1]),
                                  fmaxf(acc[mt][3][2*half], acc[mt][3][2*half+1])));
                        if (m > td[li][2]) {
                            #pragma unroll
                            for (int nt = 0; nt < 4; nt++)
                                #pragma unroll
                                for (int c = 0; c < 2; c++) {
                                    float s = acc[mt][nt][2*half + c];
                                    int ge = ebase + wn * 32 + nt * 8 + tid4 * 2 + c;
                                    insL(s, ge, td[li][0], ti[li][0],
                                         td[li][1], ti[li][1], td[li][2], ti[li][2]);
                                }
                        }
                    }
                }
            }
            __syncthreads();

            // local merge -> 48/row in smem (SM_X region, X done for this block)
            float* cd = (float*)smc;
            int*   ci = (int*)(smc + 24576);
            const int slot16 = wn * 4 + tid4;
            #pragma unroll
            for (int mt = 0; mt < 2; mt++)
                #pragma unroll
                for (int half = 0; half < 2; half++) {
                    int li = mt * 2 + half;
                    int row = wm * 32 + g8 + half * 8 + mt * 16;
                    #pragma unroll
                    for (int q = 0; q < 3; q++) {
                        cd[row * 48 + slot16 * 3 + q] = -td[li][q];
                        ci[row * 48 + slot16 * 3 + q] = ti[li][q];
                    }
                }
            __syncthreads();
            for (int q = tid; q < TM * 48; q += NTHR) {
                g_cd[(size_t)b * TM * 48 + q] = cd[q];
                g_ci[(size_t)b * TM * 48 + q] = ci[q];
            }
            __threadfence();
            __syncthreads();
            if (tid == 0) atomicExch(&g_cflag[b], 1);
        }
        return;
    }

    // ===================== PRIMARY / CLASS CTAs =============================
    const float* Xf; int ntiles, gbase_e, valid, gbase, lslot;
    const bool isprim = (blockIdx.x < NBLK);
    const int  b = blockIdx.x;
    if (!isprim) {   // class CTA (blockIdx == 128)
        Xf = feats;  ntiles = NC / TN;  gbase_e = 0;
        valid = 64;  gbase = 0;  lslot = 0;
    } else {
        Xf = feats + (size_t)(64 + b * TM) * D;
        ntiles = NT_P;  gbase_e = NC;
        valid = TM;  gbase = 64 + b * TM;  lslot = 1;
    }

    // convert X block to augmented bf16 smem; primaries also publish to gmem
    for (int q = tid; q < TM * 35; q += NTHR) {
        int row = q / 35, ch = q - row * 35;
        uint4 pv = make_uint4(0u, 0u, 0u, 0u);
        if (ch < 32) {
            if (row < valid) {
                const float4* xs = (const float4*)(Xf + (size_t)row * D + ch * 8);
                float4 a = xs[0], bb = xs[1];
                pv.x = pk(a.x, a.y);  pv.y = pk(a.z, a.w);
                pv.z = pk(bb.x, bb.y); pv.w = pk(bb.z, bb.w);
            }
        } else if (ch == 32) {
            pv.x = 0x3F803F80u;
        }
        *(uint4*)(smc + SM_X + (size_t)row * SXB + ch * 16) = pv;
        if (isprim) ((uint4*)(g_xbf + (size_t)b * TILE_B))[q] = pv;
    }
    __threadfence();
    __syncthreads();
    if (tid == 0) {
        if (isprim) atomicExch(&g_xready[b], 1);
        MBAR_EXPECT_TX(full0, TILE_B);
        BULK_CP(sbase + SM_E0, g_ebf + (size_t)gbase_e * SXB, TILE_B, full0);
        MBAR_EXPECT_TX(full1, TILE_B);
        BULK_CP(sbase + SM_E1, g_ebf + (size_t)(gbase_e + TN) * SXB, TILE_B, full1);
    }

    float td[4][3]; int ti[4][3];
    #pragma unroll
    for (int li = 0; li < 4; li++)
        #pragma unroll
        for (int q = 0; q < 3; q++) { td[li][q] = -FLT_MAX; ti[li][q] = 0x7fffffff; }

    for (int t = 0; t < ntiles; t++) {
        const int bsel = t & 1;
        const uint32_t fullb  = bsel ? full1 : full0;
        const uint32_t emptyb = bsel ? empty1 : empty0;
        MBAR_WAIT(fullb, (uint32_t)((t >> 1) & 1));
        const uint32_t eb = sbase + (bsel ? SM_E1 : SM_E0);

        float acc[2][4][4];
        #pragma unroll
        for (int mt = 0; mt < 2; mt++)
            #pragma unroll
            for (int nt = 0; nt < 4; nt++)
                #pragma unroll
                for (int q = 0; q < 4; q++) acc[mt][nt][q] = 0.f;

        uint32_t af[2][2][4], bf[2][2][4];
        LDSM4(af[0][0], xb + aoff0);
        LDSM4(af[0][1], xb + aoff1);
        LDSM4(bf[0][0], eb + boff0);
        LDSM4(bf[0][1], eb + boff1);
        #pragma unroll
        for (int ks = 0; ks < KSTEPS; ks++) {
            const int cur = ks & 1, nxt = cur ^ 1;
            const uint32_t kb = (ks + 1) * 32;
            const bool more = (ks < KSTEPS - 1);
            if (more) LDSM4(af[nxt][0], xb + aoff0 + kb);
            MMA16816(acc[0][0], af[cur][0], bf[cur][0][0], bf[cur][0][1]);
            MMA16816(acc[0][1], af[cur][0], bf[cur][0][2], bf[cur][0][3]);
            if (more) LDSM4(af[nxt][1], xb + aoff1 + kb);
            MMA16816(acc[1][0], af[cur][1], bf[cur][0][0], bf[cur][0][1]);
            MMA16816(acc[1][1], af[cur][1], bf[cur][0][2], bf[cur][0][3]);
            if (more) LDSM4(bf[nxt][0], eb + boff0 + kb);
            MMA16816(acc[0][2], af[cur][0], bf[cur][1][0], bf[cur][1][1]);
            MMA16816(acc[0][3], af[cur][0], bf[cur][1][2], bf[cur][1][3]);
            if (more) LDSM4(bf[nxt][1], eb + boff1 + kb);
            MMA16816(acc[1][2], af[cur][1], bf[cur][1][0], bf[cur][1][1]);
            MMA16816(acc[1][3], af[cur][1], bf[cur][1][2], bf[cur][1][3]);
        }
        if (lane == 0) MBAR_ARRIVE(emptyb);
        if (t + 2 < ntiles && tid == 0) {
            MBAR_WAIT(emptyb, (uint32_t)((t >> 1) & 1));
            MBAR_EXPECT_TX(fullb, TILE_B);
            BULK_CP(eb, g_ebf + (size_t)(gbase_e + (t + 2) * TN) * SXB,
                    TILE_B, fullb);
        }
        const int ebase = gbase_e + t * TN;
        #pragma unroll
        for (int mt = 0; mt < 2; mt++) {
            #pragma unroll
            for (int half = 0; half < 2; half++) {
                const int li = mt * 2 + half;
                float m = fmaxf(
                    fmaxf(fmaxf(acc[mt][0][2*half], acc[mt][0][2*half+1]),
                          fmaxf(acc[mt][1][2*half], acc[mt][1][2*half+1])),
                    fmaxf(fmaxf(acc[mt][2][2*half], acc[mt][2][2*half+1]),
                          fmaxf(acc[mt][3][2*half], acc[mt][3][2*half+1])));
                if (m > td[li][2]) {
                    #pragma unroll
                    for (int nt = 0; nt < 4; nt++)
                        #pragma unroll
                        for (int c = 0; c < 2; c++) {
                            float s = acc[mt][nt][2*half + c];
                            int ge = ebase + wn * 32 + nt * 8 + tid4 * 2 + c;
                            insL(s, ge, td[li][0], ti[li][0],
                                 td[li][1], ti[li][1], td[li][2], ti[li][2]);
                        }
                }
            }
        }
    }
    __syncthreads();

    // ---------------- merge: own 48 + helper 48 -> 96 cands per row ----------
    float* cd  = (float*)smc;                    // [128][96] floats (49152 B)
    int*   ci  = (int*)(smc + 49152);            // [128][96] ints
    float* cd8 = (float*)(smc + 98304);          // [128][8]
    int*   ci8 = (int*)(smc + 102400);           // [128][8]
    int*   sel = (int*)(smc + 106496);           // [128][3]

    const int slot16 = wn * 4 + tid4;
    #pragma unroll
    for (int mt = 0; mt < 2; mt++)
        #pragma unroll
        for (int half = 0; half < 2; half++) {
            int li = mt * 2 + half;
            int row = wm * 32 + g8 + half * 8 + mt * 16;
            #pragma unroll
            for (int q = 0; q < 3; q++) {
                cd[row * 96 + slot16 * 3 + q] = -td[li][q];
                ci[row * 96 + slot16 * 3 + q] = ti[li][q];
            }
        }
    if (isprim) {
        if (tid == 0) { while (atomicAdd(&g_cflag[b], 0) == 0) {} }
        __syncthreads();
        __threadfence();
        for (int q = tid; q < TM * 48; q += NTHR) {
            int row = q / 48, c = q - row * 48;
            cd[row * 96 + 48 + c] = g_cd[(size_t)b * TM * 48 + q];
            ci[row * 96 + 48 + c] = g_ci[(size_t)b * TM * 48 + q];
        }
    } else {
        for (int q = tid; q < TM * 48; q += NTHR) {
            int row = q / 48, c = q - row * 48;
            cd[row * 96 + 48 + c] = FLT_MAX;
            ci[row * 96 + 48 + c] = 0x7fffffff;
        }
    }
    __syncthreads();

    // approx top-8 of 96 (selection with tie-break; destructive)
    if (tid < valid) {
        for (int s = 0; s < 8; s++) {
            float bd = FLT_MAX; int bi = 0x7fffffff; int bj = -1;
            for (int j = 0; j < 96; j++) {
                float dv = cd[tid * 96 + j]; int iv = ci[tid * 96 + j];
                if (dlt(dv, iv, bd, bi)) { bd = dv; bi = iv; bj = j; }
            }
            cd[tid * 96 + bj] = FLT_MAX; ci[tid * 96 + bj] = 0x7fffffff;
            cd8[tid * 8 + s] = bd;  ci8[tid * 8 + s] = bi;
        }
    }
    __syncthreads();

    // exact fp32 rescore of 8 candidates per row
    for (int it = wid; it < valid * 8; it += NWARP) {
        int row = it >> 3, c = it & 7;
        int idx = ci8[row * 8 + c];
        const float* erow = (idx < NC) ? (Ec + (size_t)idx * D)
                                       : (Ef + (size_t)(idx - NC) * D);
        const float4* e4 = (const float4*)erow;
        const float4* x4 = (const float4*)(Xf + (size_t)row * D);
        float4 ea = e4[lane * 2], ebv = e4[lane * 2 + 1];
        float4 xa = x4[lane * 2], xbv = x4[lane * 2 + 1];
        float dot = ea.x*xa.x + ea.y*xa.y + ea.z*xa.z + ea.w*xa.w
                  + ebv.x*xbv.x + ebv.y*xbv.y + ebv.z*xbv.z + ebv.w*xbv.w;
        #pragma unroll
        for (int o = 16; o > 0; o >>= 1) dot += __shfl_xor_sync(0xffffffffu, dot, o);
        if (lane == 0) cd8[row * 8 + c] = g_e2[idx] - 2.f * dot;
    }
    __syncthreads();

    if (tid < valid) {
        float d0 = FLT_MAX, d1 = FLT_MAX, d2 = FLT_MAX;
        int   i0 = 0x7fffffff, i1 = 0x7fffffff, i2 = 0x7fffffff;
        #pragma unroll
        for (int s = 0; s < 8; s++)
            ins3(cd8[tid * 8 + s], ci8[tid * 8 + s], d0, i0, d1, i1, d2, i2);
        sel[tid * 3 + 0] = i0;
        sel[tid * 3 + 1] = i1;
        sel[tid * 3 + 2] = i2;
    }
    __syncthreads();

    // gather + write quantized/indices + loss + counts
    float lsum = 0.f;
    for (int j = wid; j < valid * 3; j += NWARP) {
        int r  = j / 3;
        int kk = j - r * 3;
        int idx = sel[j];
        int g  = gbase + r;
        const float* erow = (idx < NC) ? (Ec + (size_t)idx * D)
                                       : (Ef + (size_t)(idx - NC) * D);
        const float4* e4 = (const float4*)erow;
        const float4* x4 = (const float4*)(Xf + (size_t)r * D);
        float4 v0 = e4[lane * 2], v1 = e4[lane * 2 + 1];
        float4 x0 = x4[lane * 2], x1 = x4[lane * 2 + 1];
        size_t qb = QOFF + ((size_t)g * 3 + kk) * D + lane * 8;
        out[qb + 0] = v0.x; out[qb + 1] = v0.y; out[qb + 2] = v0.z; out[qb + 3] = v0.w;
        out[qb + 4] = v1.x; out[qb + 5] = v1.y; out[qb + 6] = v1.z; out[qb + 7] = v1.w;
        float dx;
        dx = v0.x - x0.x; lsum += dx * dx;
        dx = v0.y - x0.y; lsum += dx * dx;
        dx = v0.z - x0.z; lsum += dx * dx;
        dx = v0.w - x0.w; lsum += dx * dx;
        dx = v1.x - x1.x; lsum += dx * dx;
        dx = v1.y - x1.y; lsum += dx * dx;
        dx = v1.z - x1.z; lsum += dx * dx;
        dx = v1.w - x1.w; lsum += dx * dx;
        if (lane == 0) {
            out[ENC_OFF + (size_t)g * 3 + kk] = (float)idx;
            atomicAdd(&g_counts[idx], 1);
        }
    }
    #pragma unroll
    for (int o = 16; o > 0; o >>= 1) lsum += __shfl_xor_sync(0xffffffffu, lsum, o);
    if (lane == 0) atomicAdd(&g_loss[lslot], (double)lsum);

    // last-CTA-done finalize (129 writers: primaries + class)
    __shared__ int s_last;
    __syncthreads();
    __threadfence();
    if (tid == 0) {
        int old = atomicAdd(&g_done, 1);
        s_last = (old == NCTA_FIN - 1) ? 1 : 0;
    }
    __syncthreads();
    if (s_last) {
        __threadfence();
        float hf = 0.f, hc = 0.f;
        for (int i = tid; i < NF; i += NTHR) {
            float avg = (float)g_counts[NC + i] * (1.0f / 16384.0f);
            hf += avg * logf(avg + 1e-10f);
        }
        for (int i = tid; i < NC; i += NTHR) {
            float avgc = (float)g_counts[i] * (1.0f / 64.0f);
            hc += avgc * logf(avgc + 1e-10f);
        }
        __shared__ float redf[16], redc[16];
        #pragma unroll
        for (int o = 16; o > 0; o >>= 1) {
            hf += __shfl_xor_sync(0xffffffffu, hf, o);
            hc += __shfl_xor_sync(0xffffffffu, hc, o);
        }
        if (lane == 0) { redf[wid] = hf; redc[wid] = hc; }
        __syncthreads();
        if (tid < 32) {
            float f = (tid < 16) ? redf[tid] : 0.f;
            float c = (tid < 16) ? redc[tid] : 0.f;
            #pragma unroll
            for (int o = 8; o > 0; o >>= 1) {
                f += __shfl_xor_sync(0xffffffffu, f, o);
                c += __shfl_xor_sync(0xffffffffu, c, o);
            }
            if (tid == 0) {
                out[FPERP_OFF] = expf(-f);
                out[CPERP_OFF] = expf(-c);
                out[0] = (float)(1.25 * (g_loss[0] / (64.0 * 3.0 * 256.0)
                                       + g_loss[1] / (16384.0 * 3.0 * 256.0)));
            }
        }
    }
}

// ---------------------------------------------------------------- launcher
extern "C" void kernel_launch(void* const* d_in, const int* in_sizes, int n_in,
                              void* d_out, int out_size) {
    (void)in_sizes; (void)n_in; (void)out_size;
    const float* feats = (const float*)d_in[0];
    const float* Ec    = (const float*)d_in[1];
    const float* Ef    = (const float*)d_in[2];
    float* out = (float*)d_out;

    cudaFuncSetAttribute(vq_main, cudaFuncAttributeMaxDynamicSharedMemorySize, SM_TOTAL);

    vq_prep<<<NTOT / 8, 256>>>(Ec, Ef);
    vq_main<<<NBLK + 1 + NHELP, NTHR, SM_TOTAL>>>(feats, Ec, Ef, out);
}